// round 2
// baseline (speedup 1.0000x reference)
#include <cuda_runtime.h>
#include <cuda_bf16.h>
#include <cstdint>

// Problem constants
#define BATCH   8192
#define IDIM    768
#define JDIM    768
#define GRID_G  5
#define KDIM    (IDIM * GRID_G)   // 3840

// GEMM tiling
#define BM 128
#define BN 128
#define BK 32
#define ASTR (BK + 4)    // 36: conflict-free A fragment loads
#define BSTR (BN + 4)    // 132: conflict-free B fragment loads
#define GEMM_THREADS 256
#define SMEM_FLOATS (2 * BM * ASTR + 2 * BK * BSTR)
#define SMEM_BYTES  (SMEM_FLOATS * 4)

// Scratch (device globals -- no allocation allowed)
__device__ float g_basis[(size_t)BATCH * KDIM];   // 126 MB
__device__ float g_wp[(size_t)KDIM * JDIM];       // 11.8 MB
__device__ float g_bias[JDIM];

__device__ __forceinline__ float to_tf32(float x) {
    uint32_t u;
    asm("cvt.rna.tf32.f32 %0, %1;" : "=r"(u) : "f"(x));
    return __uint_as_float(u);
}

__device__ __forceinline__ void cp16(float* dst, const float* src) {
    uint32_t d = (uint32_t)__cvta_generic_to_shared(dst);
    asm volatile("cp.async.cg.shared.global [%0], [%1], 16;\n" :: "r"(d), "l"(src));
}
__device__ __forceinline__ void cp_commit() {
    asm volatile("cp.async.commit_group;\n" ::: "memory");
}
template <int N>
__device__ __forceinline__ void cp_wait() {
    asm volatile("cp.async.wait_group %0;\n" :: "n"(N) : "memory");
}

__device__ __forceinline__ void mma_tf32(float c[4], const uint32_t a[4], const uint32_t b[2]) {
    asm volatile(
        "mma.sync.aligned.m16n8k8.row.col.f32.tf32.tf32.f32 "
        "{%0,%1,%2,%3}, {%4,%5,%6,%7}, {%8,%9}, {%0,%1,%2,%3};\n"
        : "+f"(c[0]), "+f"(c[1]), "+f"(c[2]), "+f"(c[3])
        : "r"(a[0]), "r"(a[1]), "r"(a[2]), "r"(a[3]), "r"(b[0]), "r"(b[1]));
}

// ---------------------------------------------------------------------------
// Kernel 1: pack weights  Wp[(i*5+g)*J + j] = tf32(coeffs[i,j,g] * scale[i,j])
// ---------------------------------------------------------------------------
__global__ void pack_kernel(const float* __restrict__ coeffs,
                            const float* __restrict__ scale) {
    int idx = blockIdx.x * blockDim.x + threadIdx.x;   // over I*J
    if (idx >= IDIM * JDIM) return;
    int i = idx / JDIM;
    int j = idx - i * JDIM;
    float s = scale[idx];
    const float* c = coeffs + (size_t)idx * GRID_G;
    #pragma unroll
    for (int g = 0; g < GRID_G; ++g) {
        g_wp[(size_t)(i * GRID_G + g) * JDIM + j] = to_tf32(c[g] * s);
    }
}

// ---------------------------------------------------------------------------
// Kernel 2: bias[j] = sum_i shift[i,j]
// ---------------------------------------------------------------------------
__global__ void bias_kernel(const float* __restrict__ shift) {
    int j = blockIdx.x * blockDim.x + threadIdx.x;
    if (j >= JDIM) return;
    float s = 0.f;
    #pragma unroll 4
    for (int i = 0; i < IDIM; ++i) s += shift[(size_t)i * JDIM + j];
    g_bias[j] = s;
}

// ---------------------------------------------------------------------------
// Kernel 3: basis[b, i*5+g] = tf32(exp(-5 * (tanh(x[b,i]) - grid[g])^2))
// ---------------------------------------------------------------------------
__global__ void basis_kernel(const float* __restrict__ x) {
    int idx = blockIdx.x * blockDim.x + threadIdx.x;   // over BATCH*IDIM
    if (idx >= BATCH * IDIM) return;
    float t = tanhf(x[idx]);
    int b = idx / IDIM;
    int i = idx - b * IDIM;
    float* dst = g_basis + (size_t)b * KDIM + i * GRID_G;
    #pragma unroll
    for (int g = 0; g < GRID_G; ++g) {
        float gv = -1.0f + 0.5f * (float)g;
        float d = t - gv;
        dst[g] = to_tf32(__expf(-5.0f * d * d));
    }
}

// ---------------------------------------------------------------------------
// Kernel 4: C[b,j] = sum_k basis[b,k] * Wp[k,j] + bias[j]
// TF32 mma.sync m16n8k8, 128x128x32 CTA tile, cp.async double buffer.
// ---------------------------------------------------------------------------
__global__ __launch_bounds__(GEMM_THREADS, 2)
void gemm_kernel(float* __restrict__ C) {
    extern __shared__ float smem[];
    // layout: As[0], As[1], Bs[0], Bs[1]
    float* AsBase = smem;
    float* BsBase = smem + 2 * BM * ASTR;

    const int tid  = threadIdx.x;
    const int lane = tid & 31;
    const int wid  = tid >> 5;
    const int wm   = (wid >> 2) * 64;   // warp row offset within CTA tile
    const int wn   = (wid & 3) * 32;    // warp col offset
    const int bm0  = blockIdx.y * BM;
    const int bn0  = blockIdx.x * BN;

    // staging indices
    const int arow = tid >> 3;          // 0..31 (+32q)
    const int ac4  = (tid & 7) * 4;     // 0..28
    const int brow = tid >> 5;          // 0..7 (+8q)
    const int bc4  = (tid & 31) * 4;    // 0..124

    float acc[4][4][4];
    #pragma unroll
    for (int mt = 0; mt < 4; ++mt)
        #pragma unroll
        for (int nt = 0; nt < 4; ++nt)
            #pragma unroll
            for (int r = 0; r < 4; ++r) acc[mt][nt][r] = 0.f;

    const int NT = KDIM / BK;   // 120

    // stage tile 0 into buffer 0
    {
        const float* asrc = g_basis + (size_t)(bm0 + arow) * KDIM + ac4;
        float* adst = AsBase + arow * ASTR + ac4;
        #pragma unroll
        for (int q = 0; q < 4; ++q) cp16(adst + q * 32 * ASTR, asrc + (size_t)q * 32 * KDIM);
        const float* bsrc = g_wp + (size_t)brow * JDIM + bn0 + bc4;
        float* bdst = BsBase + brow * BSTR + bc4;
        #pragma unroll
        for (int q = 0; q < 4; ++q) cp16(bdst + q * 8 * BSTR, bsrc + (size_t)q * 8 * JDIM);
        cp_commit();
    }

    for (int kt = 0; kt < NT; ++kt) {
        const int cur = kt & 1;
        if (kt + 1 < NT) {
            const int nxt = cur ^ 1;
            const int kk = (kt + 1) * BK;
            const float* asrc = g_basis + (size_t)(bm0 + arow) * KDIM + kk + ac4;
            float* adst = AsBase + nxt * (BM * ASTR) + arow * ASTR + ac4;
            #pragma unroll
            for (int q = 0; q < 4; ++q) cp16(adst + q * 32 * ASTR, asrc + (size_t)q * 32 * KDIM);
            const float* bsrc = g_wp + (size_t)(kk + brow) * JDIM + bn0 + bc4;
            float* bdst = BsBase + nxt * (BK * BSTR) + brow * BSTR + bc4;
            #pragma unroll
            for (int q = 0; q < 4; ++q) cp16(bdst + q * 8 * BSTR, bsrc + (size_t)q * 8 * JDIM);
            cp_commit();
            cp_wait<1>();   // tile kt complete, kt+1 may be in flight
        } else {
            cp_wait<0>();
        }
        __syncthreads();

        const float* as = AsBase + cur * (BM * ASTR);
        const float* bs = BsBase + cur * (BK * BSTR);

        #pragma unroll
        for (int ks = 0; ks < BK / 8; ++ks) {
            const int k0 = ks * 8;
            uint32_t af[4][4];
            #pragma unroll
            for (int mt = 0; mt < 4; ++mt) {
                const float* ap = as + (wm + mt * 16 + (lane >> 2)) * ASTR + k0 + (lane & 3);
                af[mt][0] = __float_as_uint(ap[0]);
                af[mt][1] = __float_as_uint(ap[8 * ASTR]);
                af[mt][2] = __float_as_uint(ap[4]);
                af[mt][3] = __float_as_uint(ap[8 * ASTR + 4]);
            }
            uint32_t bf[4][2];
            #pragma unroll
            for (int nt = 0; nt < 4; ++nt) {
                const float* bp = bs + (k0 + (lane & 3)) * BSTR + wn + nt * 8 + (lane >> 2);
                bf[nt][0] = __float_as_uint(bp[0]);
                bf[nt][1] = __float_as_uint(bp[4 * BSTR]);
            }
            #pragma unroll
            for (int mt = 0; mt < 4; ++mt)
                #pragma unroll
                for (int nt = 0; nt < 4; ++nt)
                    mma_tf32(acc[mt][nt], af[mt], bf[nt]);
        }
        __syncthreads();
    }

    // epilogue: add bias, write out
    #pragma unroll
    for (int mt = 0; mt < 4; ++mt) {
        const int r0 = bm0 + wm + mt * 16 + (lane >> 2);
        #pragma unroll
        for (int nt = 0; nt < 4; ++nt) {
            const int c0 = bn0 + wn + nt * 8 + 2 * (lane & 3);
            const float bv0 = g_bias[c0];
            const float bv1 = g_bias[c0 + 1];
            float2 v0 = make_float2(acc[mt][nt][0] + bv0, acc[mt][nt][1] + bv1);
            float2 v1 = make_float2(acc[mt][nt][2] + bv0, acc[mt][nt][3] + bv1);
            *reinterpret_cast<float2*>(C + (size_t)r0 * JDIM + c0) = v0;
            *reinterpret_cast<float2*>(C + (size_t)(r0 + 8) * JDIM + c0) = v1;
        }
    }
}

// ---------------------------------------------------------------------------
extern "C" void kernel_launch(void* const* d_in, const int* in_sizes, int n_in,
                              void* d_out, int out_size) {
    const float* x      = (const float*)d_in[0];
    const float* coeffs = (const float*)d_in[1];
    const float* scale  = (const float*)d_in[2];
    const float* shift  = (const float*)d_in[3];
    float* out = (float*)d_out;

    pack_kernel<<<(IDIM * JDIM + 255) / 256, 256>>>(coeffs, scale);
    bias_kernel<<<(JDIM + 255) / 256, 256>>>(shift);
    basis_kernel<<<(BATCH * IDIM + 255) / 256, 256>>>(x);

    cudaFuncSetAttribute(gemm_kernel, cudaFuncAttributeMaxDynamicSharedMemorySize, SMEM_BYTES);
    gemm_kernel<<<dim3(JDIM / BN, BATCH / BM), GEMM_THREADS, SMEM_BYTES>>>(out);
}

// round 6
// speedup vs baseline: 1.1460x; 1.1460x over previous
#include <cuda_runtime.h>
#include <cuda_fp16.h>
#include <cstdint>

// ---------------------------------------------------------------- constants
#define BATCH   8192
#define IDIM    768
#define JDIM    768
#define GRID_G  5
#define KDIM    (IDIM * GRID_G)      // 3840

#define BM 128
#define BN 128
#define BKH 64                        // fp16 elems per K chunk -> 128B rows
#define NITER (KDIM / BKH)            // 60
#define TILE_B (128 * 128)            // 16KB per tile
#define SMEM_DYN (4 * TILE_B + 1024)  // A0,A1,B0,B1 + align pad

// fp16 scratch (device globals -- no allocation allowed)
__device__ __half g_basis[(size_t)BATCH * KDIM];   // 63 MB   A[b][k]
__device__ __half g_wt[(size_t)JDIM * KDIM];       // 5.9 MB  W^T[j][k]
__device__ float  g_bias[JDIM];

// ---------------------------------------------------------------- helpers
__device__ __forceinline__ uint32_t smem_u32(const void* p) {
    uint32_t a;
    asm("{ .reg .u64 t; cvta.to.shared.u64 t, %1; cvt.u32.u64 %0, t; }" : "=r"(a) : "l"(p));
    return a;
}
__device__ __forceinline__ void cp16(uint32_t dst, const void* src) {
    asm volatile("cp.async.cg.shared.global [%0], [%1], 16;\n" :: "r"(dst), "l"(src));
}
__device__ __forceinline__ void cp_commit() {
    asm volatile("cp.async.commit_group;\n" ::: "memory");
}
template <int N>
__device__ __forceinline__ void cp_wait() {
    asm volatile("cp.async.wait_group %0;\n" :: "n"(N) : "memory");
}
__device__ __forceinline__ void ldsm_x4(uint32_t& r0, uint32_t& r1, uint32_t& r2, uint32_t& r3,
                                        uint32_t addr) {
    asm volatile("ldmatrix.sync.aligned.m8n8.x4.shared.b16 {%0,%1,%2,%3}, [%4];"
                 : "=r"(r0), "=r"(r1), "=r"(r2), "=r"(r3) : "r"(addr));
}
__device__ __forceinline__ void mma16816(float c[4], const uint32_t a[4], const uint32_t b[2]) {
    asm volatile(
        "mma.sync.aligned.m16n8k16.row.col.f32.f16.f16.f32 "
        "{%0,%1,%2,%3}, {%4,%5,%6,%7}, {%8,%9}, {%0,%1,%2,%3};\n"
        : "+f"(c[0]), "+f"(c[1]), "+f"(c[2]), "+f"(c[3])
        : "r"(a[0]), "r"(a[1]), "r"(a[2]), "r"(a[3]), "r"(b[0]), "r"(b[1]));
}

// ---------------------------------------------------------------------------
// Kernel 1: pack W^T  g_wt[j][i*5+g] = fp16(coeffs[i,j,g] * scale[i,j])
// thread per (i,j), j fastest: coalesced reads; 10B contiguous writes.
// ---------------------------------------------------------------------------
__global__ void pack_kernel(const float* __restrict__ coeffs,
                            const float* __restrict__ scale) {
    int idx = blockIdx.x * blockDim.x + threadIdx.x;   // i*JDIM + j
    if (idx >= IDIM * JDIM) return;
    int i = idx / JDIM;
    int j = idx - i * JDIM;
    float s = scale[idx];
    const float* c = coeffs + (size_t)idx * GRID_G;
    __half* dst = g_wt + (size_t)j * KDIM + i * GRID_G;
    #pragma unroll
    for (int g = 0; g < GRID_G; ++g) dst[g] = __float2half_rn(c[g] * s);
}

// ---------------------------------------------------------------------------
// Kernel 2: bias[j] = sum_i shift[i,j]
// ---------------------------------------------------------------------------
__global__ void bias_kernel(const float* __restrict__ shift) {
    int j = blockIdx.x * blockDim.x + threadIdx.x;
    if (j >= JDIM) return;
    float s = 0.f;
    #pragma unroll 4
    for (int i = 0; i < IDIM; ++i) s += shift[(size_t)i * JDIM + j];
    g_bias[j] = s;
}

// ---------------------------------------------------------------------------
// Kernel 3: basis (fp16).  t=tanh(x); p=e^{-5t^2}; u=e^{5t}; v=1/u
//   exp(-5(t - grid_g)^2) = p * c_g * u^{2*grid_g};  grid = {-1,-.5,0,.5,1}
//   c1 = e^-1.25, c2 = e^-5.   4 MUFU per element.
// ---------------------------------------------------------------------------
__global__ void basis_kernel(const float* __restrict__ x) {
    int idx = blockIdx.x * blockDim.x + threadIdx.x;   // b*IDIM + i
    if (idx >= BATCH * IDIM) return;
    float xv = x[idx];
    float t;
    asm("tanh.approx.f32 %0, %1;" : "=f"(t) : "f"(xv));
    const float L5 = 7.21347520444482f;                // 5*log2(e)
    float a = L5 * t;
    float u, p, v;
    asm("ex2.approx.ftz.f32 %0, %1;" : "=f"(u) : "f"(a));
    float na = -a * t;                                  // -5*log2(e)*t^2
    asm("ex2.approx.ftz.f32 %0, %1;" : "=f"(p) : "f"(na));
    asm("rcp.approx.ftz.f32 %0, %1;" : "=f"(v) : "f"(u));
    const float c1 = 0.2865047968601901f;               // e^-1.25
    const float c2 = 0.006737946999085467f;             // e^-5
    __half* dst = g_basis + (size_t)idx * GRID_G;
    dst[0] = __float2half_rn(p * c2 * v * v);
    dst[1] = __float2half_rn(p * c1 * v);
    dst[2] = __float2half_rn(p);
    dst[3] = __float2half_rn(p * c1 * u);
    dst[4] = __float2half_rn(p * c2 * u * u);
}

// ---------------------------------------------------------------------------
// Kernel 4: GEMM  C[b,j] = sum_k A[b,k] W^T[j,k] + bias[j]
// fp16 mma.sync m16n8k16, 128x128 CTA, K chunks of 64, cp.async double buffer,
// XOR-swizzled smem + ldmatrix.x4 fragment loads (conflict-free).
// ---------------------------------------------------------------------------
__global__ __launch_bounds__(256, 2)
void gemm_kernel(float* __restrict__ C) {
    extern __shared__ char dsmem[];
    const uint32_t sbase = (smem_u32(dsmem) + 1023u) & ~1023u;
    // A stages: sbase + s*TILE_B ; B stages: sbase + (2+s)*TILE_B

    const int tid  = threadIdx.x;
    const int lane = tid & 31;
    const int wid  = tid >> 5;
    const int wm   = (wid >> 1) * 32;     // 4 warp-rows x 2 warp-cols
    const int wn   = (wid & 1) * 64;
    const int bm0  = blockIdx.y * BM;
    const int bn0  = blockIdx.x * BN;

    // staging: each thread: row srow+32q, 16-byte segment sseg, q=0..3 (per tile)
    const int srow = tid >> 3;                       // 0..31
    const int sseg = (tid & 7) * 16;                 // byte col 0..112
    const uint32_t swcol = (uint32_t)(sseg ^ ((srow & 7) << 4));
    const __half* aglob = g_basis + (size_t)(bm0 + srow) * KDIM + (sseg >> 1);
    const __half* bglob = g_wt   + (size_t)(bn0 + srow) * KDIM + (sseg >> 1);

    float acc[2][8][4];
    #pragma unroll
    for (int mt = 0; mt < 2; ++mt)
        #pragma unroll
        for (int nt = 0; nt < 8; ++nt)
            #pragma unroll
            for (int r = 0; r < 4; ++r) acc[mt][nt][r] = 0.f;

    // ldmatrix lane addressing (non-trans, canonical m16k16 / n8k16 maps)
    const int arow0 = wm + (lane & 7) + 8 * ((lane >> 3) & 1);    // + mt*16
    const uint32_t axor = (uint32_t)((lane & 7) << 4);
    const uint32_t acol = (uint32_t)(16 * (lane >> 4));           // + 32*ks
    const int brow0 = wn + (lane & 7) + 8 * (lane >> 4);          // + jg*16
    const uint32_t bcol = (uint32_t)(16 * ((lane >> 3) & 1));     // + 32*ks

    // prologue: stage chunk 0 into buffer 0
    {
        #pragma unroll
        for (int q = 0; q < 4; ++q) {
            cp16(sbase + (srow + 32 * q) * 128 + swcol, aglob + (size_t)(32 * q) * KDIM);
            cp16(sbase + 2 * TILE_B + (srow + 32 * q) * 128 + swcol, bglob + (size_t)(32 * q) * KDIM);
        }
        cp_commit();
    }

    for (int kt = 0; kt < NITER; ++kt) {
        const int cur = kt & 1;
        if (kt + 1 < NITER) {
            const int nxt = cur ^ 1;
            const int kh = (kt + 1) * BKH;
            #pragma unroll
            for (int q = 0; q < 4; ++q) {
                cp16(sbase + nxt * TILE_B + (srow + 32 * q) * 128 + swcol,
                     aglob + kh + (size_t)(32 * q) * KDIM);
                cp16(sbase + (2 + nxt) * TILE_B + (srow + 32 * q) * 128 + swcol,
                     bglob + kh + (size_t)(32 * q) * KDIM);
            }
            cp_commit();
            cp_wait<1>();
        } else {
            cp_wait<0>();
        }
        __syncthreads();

        const uint32_t abase = sbase + cur * TILE_B;
        const uint32_t bbase = sbase + (2 + cur) * TILE_B;

        #pragma unroll
        for (int ks = 0; ks < 4; ++ks) {
            uint32_t af[2][4];
            #pragma unroll
            for (int mt = 0; mt < 2; ++mt) {
                uint32_t addr = abase + (uint32_t)(arow0 + mt * 16) * 128
                              + ((acol + 32 * ks) ^ axor);
                ldsm_x4(af[mt][0], af[mt][1], af[mt][2], af[mt][3], addr);
            }
            uint32_t bf[8][2];
            #pragma unroll
            for (int jg = 0; jg < 4; ++jg) {
                uint32_t addr = bbase + (uint32_t)(brow0 + jg * 16) * 128
                              + ((bcol + 32 * ks) ^ axor);
                ldsm_x4(bf[2 * jg][0], bf[2 * jg][1], bf[2 * jg + 1][0], bf[2 * jg + 1][1], addr);
            }
            #pragma unroll
            for (int mt = 0; mt < 2; ++mt)
                #pragma unroll
                for (int nt = 0; nt < 8; ++nt)
                    mma16816(acc[mt][nt], af[mt], bf[nt]);
        }
        __syncthreads();
    }

    // epilogue: add bias, write fp32 out
    #pragma unroll
    for (int mt = 0; mt < 2; ++mt) {
        const int r0 = bm0 + wm + mt * 16 + (lane >> 2);
        #pragma unroll
        for (int nt = 0; nt < 8; ++nt) {
            const int c0 = bn0 + wn + nt * 8 + 2 * (lane & 3);
            const float bv0 = g_bias[c0];
            const float bv1 = g_bias[c0 + 1];
            float2 v0 = make_float2(acc[mt][nt][0] + bv0, acc[mt][nt][1] + bv1);
            float2 v1 = make_float2(acc[mt][nt][2] + bv0, acc[mt][nt][3] + bv1);
            *reinterpret_cast<float2*>(C + (size_t)r0 * JDIM + c0) = v0;
            *reinterpret_cast<float2*>(C + (size_t)(r0 + 8) * JDIM + c0) = v1;
        }
    }
}

// ---------------------------------------------------------------------------
extern "C" void kernel_launch(void* const* d_in, const int* in_sizes, int n_in,
                              void* d_out, int out_size) {
    const float* x      = (const float*)d_in[0];
    const float* coeffs = (const float*)d_in[1];
    const float* scale  = (const float*)d_in[2];
    const float* shift  = (const float*)d_in[3];
    float* out = (float*)d_out;

    pack_kernel<<<(IDIM * JDIM + 255) / 256, 256>>>(coeffs, scale);
    bias_kernel<<<(JDIM + 255) / 256, 256>>>(shift);
    basis_kernel<<<(BATCH * IDIM + 255) / 256, 256>>>(x);

    cudaFuncSetAttribute(gemm_kernel, cudaFuncAttributeMaxDynamicSharedMemorySize, SMEM_DYN);
    gemm_kernel<<<dim3(JDIM / BN, BATCH / BM), 256, SMEM_DYN>>>(out);
}

// round 12
// speedup vs baseline: 1.6118x; 1.4065x over previous
#include <cuda_runtime.h>
#include <cuda_fp16.h>
#include <cstdint>

// ---------------------------------------------------------------- constants
#define BATCH   8192
#define IDIM    768
#define JDIM    768
#define GRID_G  5
#define KDIM    (IDIM * GRID_G)      // 3840

#define BMT 64                        // CTA tile M
#define BNT 128                       // CTA tile N
#define BKH 64                        // fp16 K elems per chunk (128B rows)
#define NITER (KDIM / BKH)            // 60
#define MTILES (BATCH / BMT)          // 128
#define NTILES_N (JDIM / BNT)         // 6
#define NTILES (MTILES * NTILES_N)    // 768

#define A_TB (BMT * 128)              // 8KB
#define B_TB (BNT * 128)              // 16KB
#define STG 3
#define STAGE_B (A_TB + B_TB)         // 24KB
#define SMEM_DYN (STG * STAGE_B + 1024)
#define GRID_CTAS 296                 // 2 per SM x 148

// fp16 scratch (device globals -- no allocation allowed)
__device__ __half g_basis[(size_t)BATCH * KDIM];   // 63 MB   A[b][k]
__device__ __half g_wt[(size_t)JDIM * KDIM];       // 5.9 MB  W^T[j][k]
__device__ float  g_bias[JDIM];
__device__ unsigned int g_ticket;

// ---------------------------------------------------------------- helpers
__device__ __forceinline__ uint32_t smem_u32(const void* p) {
    uint32_t a;
    asm("{ .reg .u64 t; cvta.to.shared.u64 t, %1; cvt.u32.u64 %0, t; }" : "=r"(a) : "l"(p));
    return a;
}
__device__ __forceinline__ void cp16(uint32_t dst, const void* src) {
    asm volatile("cp.async.cg.shared.global [%0], [%1], 16;\n" :: "r"(dst), "l"(src));
}
__device__ __forceinline__ void cp_commit() {
    asm volatile("cp.async.commit_group;\n" ::: "memory");
}
template <int N>
__device__ __forceinline__ void cp_wait() {
    asm volatile("cp.async.wait_group %0;\n" :: "n"(N) : "memory");
}
__device__ __forceinline__ void ldsm_x4(uint32_t& r0, uint32_t& r1, uint32_t& r2, uint32_t& r3,
                                        uint32_t addr) {
    asm volatile("ldmatrix.sync.aligned.m8n8.x4.shared.b16 {%0,%1,%2,%3}, [%4];"
                 : "=r"(r0), "=r"(r1), "=r"(r2), "=r"(r3) : "r"(addr));
}
__device__ __forceinline__ void mma16816(float c[4], const uint32_t a[4], const uint32_t b[2]) {
    asm volatile(
        "mma.sync.aligned.m16n8k16.row.col.f32.f16.f16.f32 "
        "{%0,%1,%2,%3}, {%4,%5,%6,%7}, {%8,%9}, {%0,%1,%2,%3};\n"
        : "+f"(c[0]), "+f"(c[1]), "+f"(c[2]), "+f"(c[3])
        : "r"(a[0]), "r"(a[1]), "r"(a[2]), "r"(a[3]), "r"(b[0]), "r"(b[1]));
}

// ---------------------------------------------------------------------------
// Kernel 1: pack W^T  g_wt[j][i*5+g] = fp16(coeffs[i,j,g] * scale[i,j])
// i fastest across threads -> warp writes 32x10B = 320B contiguous.
// ---------------------------------------------------------------------------
__global__ void pack_kernel(const float* __restrict__ coeffs,
                            const float* __restrict__ scale) {
    int idx = blockIdx.x * blockDim.x + threadIdx.x;   // j*IDIM + i
    if (idx >= IDIM * JDIM) return;
    int j = idx / IDIM;
    int i = idx - j * IDIM;
    float s = __ldg(scale + (size_t)i * JDIM + j);
    const float* c = coeffs + ((size_t)i * JDIM + j) * GRID_G;
    __half* dst = g_wt + (size_t)j * KDIM + i * GRID_G;
    #pragma unroll
    for (int g = 0; g < GRID_G; ++g) dst[g] = __float2half_rn(__ldg(c + g) * s);
}

// ---------------------------------------------------------------------------
// Kernel 2: bias[j] = sum_i shift[i,j]  (+ ticket reset for gemm)
// ---------------------------------------------------------------------------
__global__ void bias_kernel(const float* __restrict__ shift) {
    if (blockIdx.x == 0 && threadIdx.x == 0) g_ticket = 0u;
    int j = blockIdx.x * blockDim.x + threadIdx.x;
    if (j >= JDIM) return;
    float s = 0.f;
    #pragma unroll 4
    for (int i = 0; i < IDIM; ++i) s += shift[(size_t)i * JDIM + j];
    g_bias[j] = s;
}

// ---------------------------------------------------------------------------
// Kernel 3: basis (fp16).  t=tanh(x); p=e^{-5t^2}; u=e^{5t}; v=1/u
//   exp(-5(t - grid_g)^2) = p * c_g * u^{2*grid_g};  grid = {-1,-.5,0,.5,1}
// ---------------------------------------------------------------------------
__global__ void basis_kernel(const float* __restrict__ x) {
    int idx = blockIdx.x * blockDim.x + threadIdx.x;   // b*IDIM + i
    if (idx >= BATCH * IDIM) return;
    float xv = x[idx];
    float t;
    asm("tanh.approx.f32 %0, %1;" : "=f"(t) : "f"(xv));
    const float L5 = 7.21347520444482f;                // 5*log2(e)
    float a = L5 * t;
    float u, p, v;
    asm("ex2.approx.ftz.f32 %0, %1;" : "=f"(u) : "f"(a));
    float na = -a * t;                                  // -5*log2(e)*t^2
    asm("ex2.approx.ftz.f32 %0, %1;" : "=f"(p) : "f"(na));
    asm("rcp.approx.ftz.f32 %0, %1;" : "=f"(v) : "f"(u));
    const float c1 = 0.2865047968601901f;               // e^-1.25
    const float c2 = 0.006737946999085467f;             // e^-5
    __half* dst = g_basis + (size_t)idx * GRID_G;
    dst[0] = __float2half_rn(p * c2 * v * v);
    dst[1] = __float2half_rn(p * c1 * v);
    dst[2] = __float2half_rn(p);
    dst[3] = __float2half_rn(p * c1 * u);
    dst[4] = __float2half_rn(p * c2 * u * u);
}

// ---------------------------------------------------------------------------
// Kernel 4: GEMM  C[b,j] = sum_k A[b,k] W^T[j,k] + bias[j]
// 64x128 tiles, atomic-ticket scheduler, 3-stage cp.async, 1 sync/chunk.
// ---------------------------------------------------------------------------
__global__ __launch_bounds__(256, 2)
void gemm_kernel(float* __restrict__ C) {
    extern __shared__ char dsmem[];
    __shared__ unsigned s_tile;
    const uint32_t sbase = (smem_u32(dsmem) + 1023u) & ~1023u;

    const int tid  = threadIdx.x;
    const int lane = tid & 31;
    const int wid  = tid >> 5;
    const int wm   = (wid & 1) * 32;      // 2 warp-rows x 4 warp-cols (32x32 each)
    const int wn   = (wid >> 1) * 32;

    // staging indices
    const int srow = tid >> 3;                       // 0..31
    const int sseg = (tid & 7) * 16;                 // byte col 0..112
    const uint32_t swcol = (uint32_t)(sseg ^ ((srow & 7) << 4));
    const int scol_h = sseg >> 1;                    // half offset within row

    // ldmatrix lane addressing (same verified maps as R6)
    const int arow0 = wm + (lane & 7) + 8 * ((lane >> 3) & 1);    // + mt*16
    const uint32_t axor = (uint32_t)((lane & 7) << 4);
    const uint32_t acol = (uint32_t)(16 * (lane >> 4));           // + 32*ks
    const int brow0 = wn + (lane & 7) + 8 * (lane >> 4);          // + jg*16
    const uint32_t bcol = (uint32_t)(16 * ((lane >> 3) & 1));     // + 32*ks

    for (;;) {
        if (tid == 0) s_tile = atomicAdd(&g_ticket, 1u);
        __syncthreads();                 // also guards smem reuse across tiles
        const unsigned t = s_tile;
        if (t >= NTILES) break;
        const int m0 = (int)(t / NTILES_N) * BMT;
        const int n0 = (int)(t % NTILES_N) * BNT;

        const __half* aglob = g_basis + (size_t)(m0 + srow) * KDIM + scol_h;
        const __half* bglob = g_wt   + (size_t)(n0 + srow) * KDIM + scol_h;

        float acc[2][4][4];
        #pragma unroll
        for (int mt = 0; mt < 2; ++mt)
            #pragma unroll
            for (int nt = 0; nt < 4; ++nt)
                #pragma unroll
                for (int r = 0; r < 4; ++r) acc[mt][nt][r] = 0.f;

        // prologue: chunks 0 and 1
        #pragma unroll
        for (int pc = 0; pc < 2; ++pc) {
            const uint32_t sb = sbase + pc * STAGE_B;
            #pragma unroll
            for (int q = 0; q < 2; ++q)
                cp16(sb + (srow + 32 * q) * 128 + swcol, aglob + pc * BKH + (size_t)(32 * q) * KDIM);
            #pragma unroll
            for (int q = 0; q < 4; ++q)
                cp16(sb + A_TB + (srow + 32 * q) * 128 + swcol, bglob + pc * BKH + (size_t)(32 * q) * KDIM);
            cp_commit();
        }

        int slot = 0, pslot = 2;
        for (int kt = 0; kt < NITER; ++kt) {
            cp_wait<1>();
            __syncthreads();

            // prefetch chunk kt+2 into pslot (overwrites chunk kt-1's slot)
            if (kt + 2 < NITER) {
                const int kh = (kt + 2) * BKH;
                const uint32_t sb = sbase + pslot * STAGE_B;
                #pragma unroll
                for (int q = 0; q < 2; ++q)
                    cp16(sb + (srow + 32 * q) * 128 + swcol, aglob + kh + (size_t)(32 * q) * KDIM);
                #pragma unroll
                for (int q = 0; q < 4; ++q)
                    cp16(sb + A_TB + (srow + 32 * q) * 128 + swcol, bglob + kh + (size_t)(32 * q) * KDIM);
            }
            cp_commit();   // always: keeps exactly 2 groups pending

            const uint32_t abase = sbase + slot * STAGE_B;
            const uint32_t bbase = abase + A_TB;

            #pragma unroll
            for (int ks = 0; ks < 4; ++ks) {
                uint32_t af[2][4];
                #pragma unroll
                for (int mt = 0; mt < 2; ++mt) {
                    uint32_t addr = abase + (uint32_t)(arow0 + mt * 16) * 128
                                  + ((acol + 32 * ks) ^ axor);
                    ldsm_x4(af[mt][0], af[mt][1], af[mt][2], af[mt][3], addr);
                }
                uint32_t bf[4][2];
                #pragma unroll
                for (int jg = 0; jg < 2; ++jg) {
                    uint32_t addr = bbase + (uint32_t)(brow0 + jg * 16) * 128
                                  + ((bcol + 32 * ks) ^ axor);
                    ldsm_x4(bf[2 * jg][0], bf[2 * jg][1], bf[2 * jg + 1][0], bf[2 * jg + 1][1], addr);
                }
                #pragma unroll
                for (int mt = 0; mt < 2; ++mt)
                    #pragma unroll
                    for (int nt = 0; nt < 4; ++nt)
                        mma16816(acc[mt][nt], af[mt], bf[nt]);
            }

            slot = (slot + 1 == STG) ? 0 : slot + 1;
            pslot = (pslot + 1 == STG) ? 0 : pslot + 1;
        }

        // epilogue: add bias, write fp32 out
        #pragma unroll
        for (int mt = 0; mt < 2; ++mt) {
            const int r0 = m0 + wm + mt * 16 + (lane >> 2);
            #pragma unroll
            for (int nt = 0; nt < 4; ++nt) {
                const int c0 = n0 + wn + nt * 8 + 2 * (lane & 3);
                const float bv0 = g_bias[c0];
                const float bv1 = g_bias[c0 + 1];
                float2 v0 = make_float2(acc[mt][nt][0] + bv0, acc[mt][nt][1] + bv1);
                float2 v1 = make_float2(acc[mt][nt][2] + bv0, acc[mt][nt][3] + bv1);
                *reinterpret_cast<float2*>(C + (size_t)r0 * JDIM + c0) = v0;
                *reinterpret_cast<float2*>(C + (size_t)(r0 + 8) * JDIM + c0) = v1;
            }
        }
    }
}

// ---------------------------------------------------------------------------
extern "C" void kernel_launch(void* const* d_in, const int* in_sizes, int n_in,
                              void* d_out, int out_size) {
    const float* x      = (const float*)d_in[0];
    const float* coeffs = (const float*)d_in[1];
    const float* scale  = (const float*)d_in[2];
    const float* shift  = (const float*)d_in[3];
    float* out = (float*)d_out;

    pack_kernel<<<(IDIM * JDIM + 255) / 256, 256>>>(coeffs, scale);
    bias_kernel<<<(JDIM + 255) / 256, 256>>>(shift);
    basis_kernel<<<(BATCH * IDIM + 255) / 256, 256>>>(x);

    cudaFuncSetAttribute(gemm_kernel, cudaFuncAttributeMaxDynamicSharedMemorySize, SMEM_DYN);
    gemm_kernel<<<GRID_CTAS, 256, SMEM_DYN>>>(out);
}

// round 14
// speedup vs baseline: 2.9170x; 1.8097x over previous
#include <cuda_runtime.h>
#include <cuda_fp16.h>
#include <cstdint>

// ---------------------------------------------------------------- constants
#define BATCH   8192
#define IDIM    768
#define JDIM    768
#define GRID_G  5
#define KDIM    (IDIM * GRID_G)      // 3840

#define BM 128                        // CTA tile M
#define BN 128                        // CTA tile N
#define BKH 64                        // fp16 K elems per chunk (128B rows)
#define NITER (KDIM / BKH)            // 60
#define MTILES (BATCH / BM)           // 64
#define NTILES_N (JDIM / BN)          // 6
#define NTILES (MTILES * NTILES_N)    // 384

#define A_TB (BM * 128)               // 16KB
#define B_TB (BN * 128)               // 16KB
#define STG 3
#define STAGE_B (A_TB + B_TB)         // 32KB
#define SMEM_DYN (STG * STAGE_B + 1024)
#define GRID_CTAS 296                 // 2 per SM x 148

// fp16 scratch (device globals -- no allocation allowed)
__device__ __half g_basis[(size_t)BATCH * KDIM];   // 63 MB   A[b][k], k = i*5+g
__device__ __half g_wt[(size_t)JDIM * KDIM];       // 5.9 MB  W^T[j][k]
__device__ float  g_bias[JDIM];
__device__ unsigned int g_ticket;

// ---------------------------------------------------------------- helpers
__device__ __forceinline__ uint32_t smem_u32(const void* p) {
    uint32_t a;
    asm("{ .reg .u64 t; cvta.to.shared.u64 t, %1; cvt.u32.u64 %0, t; }" : "=r"(a) : "l"(p));
    return a;
}
__device__ __forceinline__ void cp16(uint32_t dst, const void* src) {
    asm volatile("cp.async.cg.shared.global [%0], [%1], 16;\n" :: "r"(dst), "l"(src));
}
__device__ __forceinline__ void cp_commit() {
    asm volatile("cp.async.commit_group;\n" ::: "memory");
}
template <int N>
__device__ __forceinline__ void cp_wait() {
    asm volatile("cp.async.wait_group %0;\n" :: "n"(N) : "memory");
}
__device__ __forceinline__ void ldsm_x4(uint32_t& r0, uint32_t& r1, uint32_t& r2, uint32_t& r3,
                                        uint32_t addr) {
    asm volatile("ldmatrix.sync.aligned.m8n8.x4.shared.b16 {%0,%1,%2,%3}, [%4];"
                 : "=r"(r0), "=r"(r1), "=r"(r2), "=r"(r3) : "r"(addr));
}
__device__ __forceinline__ void mma16816(float c[4], const uint32_t a[4], const uint32_t b[2]) {
    asm volatile(
        "mma.sync.aligned.m16n8k16.row.col.f32.f16.f16.f32 "
        "{%0,%1,%2,%3}, {%4,%5,%6,%7}, {%8,%9}, {%0,%1,%2,%3};\n"
        : "+f"(c[0]), "+f"(c[1]), "+f"(c[2]), "+f"(c[3])
        : "r"(a[0]), "r"(a[1]), "r"(a[2]), "r"(a[3]), "r"(b[0]), "r"(b[1]));
}

// ---------------------------------------------------------------------------
// Kernel 1: pack W^T  g_wt[j][i*5+g] = fp16(coeffs[i,j,g] * scale[i,j])
// Also zeroes g_bias and the gemm ticket (runs first in stream order).
// ---------------------------------------------------------------------------
__global__ void pack_kernel(const float* __restrict__ coeffs,
                            const float* __restrict__ scale) {
    int idx = blockIdx.x * blockDim.x + threadIdx.x;   // j*IDIM + i
    if (idx < JDIM) g_bias[idx] = 0.f;
    if (idx == 0) g_ticket = 0u;
    if (idx >= IDIM * JDIM) return;
    int j = idx / IDIM;
    int i = idx - j * IDIM;
    float s = __ldg(scale + (size_t)i * JDIM + j);
    const float* c = coeffs + ((size_t)i * JDIM + j) * GRID_G;
    __half* dst = g_wt + (size_t)j * KDIM + i * GRID_G;
    #pragma unroll
    for (int g = 0; g < GRID_G; ++g) dst[g] = __float2half_rn(__ldg(c + g) * s);
}

// ---------------------------------------------------------------------------
// Kernel 2: bias[j] += sum over this block's 32-row i-chunk of shift[i,j]
// 24 blocks x 256 threads, coalesced reads, one atomicAdd per (block, j).
// ---------------------------------------------------------------------------
__global__ void bias_kernel(const float* __restrict__ shift) {
    const int i0 = blockIdx.x * 32;
    #pragma unroll
    for (int jj = 0; jj < 3; ++jj) {
        const int j = jj * 256 + threadIdx.x;
        float s = 0.f;
        #pragma unroll 8
        for (int ii = 0; ii < 32; ++ii)
            s += shift[(size_t)(i0 + ii) * JDIM + j];
        atomicAdd(&g_bias[j], s);
    }
}

// ---------------------------------------------------------------------------
// Kernel 3: basis (fp16), 8 i-values per thread, 5 x 16B vector stores.
//   t=tanh(x); p=e^{-5t^2}; u=e^{5t}; v=1/u
//   exp(-5(t - grid_g)^2) = p * c_g * u^{2*grid_g};  grid = {-1,-.5,0,.5,1}
// ---------------------------------------------------------------------------
__global__ void basis_kernel(const float* __restrict__ x) {
    int idx = blockIdx.x * blockDim.x + threadIdx.x;   // over BATCH*IDIM/8
    if (idx >= BATCH * IDIM / 8) return;
    const float4 x0 = *reinterpret_cast<const float4*>(x + (size_t)idx * 8);
    const float4 x1 = *reinterpret_cast<const float4*>(x + (size_t)idx * 8 + 4);
    float xs[8] = {x0.x, x0.y, x0.z, x0.w, x1.x, x1.y, x1.z, x1.w};

    union { __half h[40]; uint4 v[5]; } out;
    const float L5 = 7.21347520444482f;                 // 5*log2(e)
    const float c1 = 0.2865047968601901f;               // e^-1.25
    const float c2 = 0.006737946999085467f;             // e^-5
    #pragma unroll
    for (int e = 0; e < 8; ++e) {
        float t, u, p, v;
        asm("tanh.approx.f32 %0, %1;" : "=f"(t) : "f"(xs[e]));
        float a = L5 * t;
        asm("ex2.approx.ftz.f32 %0, %1;" : "=f"(u) : "f"(a));
        float na = -a * t;                               // -5*log2(e)*t^2
        asm("ex2.approx.ftz.f32 %0, %1;" : "=f"(p) : "f"(na));
        asm("rcp.approx.ftz.f32 %0, %1;" : "=f"(v) : "f"(u));
        out.h[e * 5 + 0] = __float2half_rn(p * c2 * v * v);
        out.h[e * 5 + 1] = __float2half_rn(p * c1 * v);
        out.h[e * 5 + 2] = __float2half_rn(p);
        out.h[e * 5 + 3] = __float2half_rn(p * c1 * u);
        out.h[e * 5 + 4] = __float2half_rn(p * c2 * u * u);
    }
    uint4* dst = reinterpret_cast<uint4*>(g_basis + (size_t)idx * 40);
    #pragma unroll
    for (int q = 0; q < 5; ++q) dst[q] = out.v[q];
}

// ---------------------------------------------------------------------------
// Kernel 4: GEMM  C[b,j] = sum_k A[b,k] W^T[j,k] + bias[j]
// 128x128 CTA tiles, 8 warps at 64x32, atomic-ticket scheduler,
// 3-stage cp.async, 1 sync per K chunk.
// ---------------------------------------------------------------------------
__global__ __launch_bounds__(256, 2)
void gemm_kernel(float* __restrict__ C) {
    extern __shared__ char dsmem[];
    __shared__ unsigned s_tile;
    const uint32_t sbase = (smem_u32(dsmem) + 1023u) & ~1023u;

    const int tid  = threadIdx.x;
    const int lane = tid & 31;
    const int wid  = tid >> 5;
    const int wm   = (wid & 1) * 64;      // 2 warp-rows x 4 warp-cols (64x32 each)
    const int wn   = (wid >> 1) * 32;

    // staging indices (per stage: A 128 rows, B 128 rows, 128B each)
    const int srow = tid >> 3;                       // 0..31
    const int sseg = (tid & 7) * 16;                 // byte col 0..112
    const uint32_t swcol = (uint32_t)(sseg ^ ((srow & 7) << 4));
    const int scol_h = sseg >> 1;                    // half offset within row

    // ldmatrix lane addressing (verified maps)
    const int arow0 = wm + (lane & 7) + 8 * ((lane >> 3) & 1);    // + mt*16
    const uint32_t axor = (uint32_t)((lane & 7) << 4);
    const uint32_t acol = (uint32_t)(16 * (lane >> 4));           // + 32*ks
    const int brow0 = wn + (lane & 7) + 8 * (lane >> 4);          // + jg*16
    const uint32_t bcol = (uint32_t)(16 * ((lane >> 3) & 1));     // + 32*ks

    for (;;) {
        if (tid == 0) s_tile = atomicAdd(&g_ticket, 1u);
        __syncthreads();                 // also guards smem reuse across tiles
        const unsigned t = s_tile;
        if (t >= NTILES) break;
        const int m0 = (int)(t / NTILES_N) * BM;
        const int n0 = (int)(t % NTILES_N) * BN;

        const __half* aglob = g_basis + (size_t)(m0 + srow) * KDIM + scol_h;
        const __half* bglob = g_wt   + (size_t)(n0 + srow) * KDIM + scol_h;

        float acc[4][4][4];
        #pragma unroll
        for (int mt = 0; mt < 4; ++mt)
            #pragma unroll
            for (int nt = 0; nt < 4; ++nt)
                #pragma unroll
                for (int r = 0; r < 4; ++r) acc[mt][nt][r] = 0.f;

        // prologue: chunks 0 and 1
        #pragma unroll
        for (int pc = 0; pc < 2; ++pc) {
            const uint32_t sb = sbase + pc * STAGE_B;
            #pragma unroll
            for (int q = 0; q < 4; ++q)
                cp16(sb + (srow + 32 * q) * 128 + swcol, aglob + pc * BKH + (size_t)(32 * q) * KDIM);
            #pragma unroll
            for (int q = 0; q < 4; ++q)
                cp16(sb + A_TB + (srow + 32 * q) * 128 + swcol, bglob + pc * BKH + (size_t)(32 * q) * KDIM);
            cp_commit();
        }

        int slot = 0, pslot = 2;
        for (int kt = 0; kt < NITER; ++kt) {
            cp_wait<1>();
            __syncthreads();

            // prefetch chunk kt+2 into pslot
            if (kt + 2 < NITER) {
                const int kh = (kt + 2) * BKH;
                const uint32_t sb = sbase + pslot * STAGE_B;
                #pragma unroll
                for (int q = 0; q < 4; ++q)
                    cp16(sb + (srow + 32 * q) * 128 + swcol, aglob + kh + (size_t)(32 * q) * KDIM);
                #pragma unroll
                for (int q = 0; q < 4; ++q)
                    cp16(sb + A_TB + (srow + 32 * q) * 128 + swcol, bglob + kh + (size_t)(32 * q) * KDIM);
            }
            cp_commit();   // always: keeps exactly 2 groups pending

            const uint32_t abase = sbase + slot * STAGE_B;
            const uint32_t bbase = abase + A_TB;

            #pragma unroll
            for (int ks = 0; ks < 4; ++ks) {
                uint32_t af[4][4];
                #pragma unroll
                for (int mt = 0; mt < 4; ++mt) {
                    uint32_t addr = abase + (uint32_t)(arow0 + mt * 16) * 128
                                  + ((acol + 32 * ks) ^ axor);
                    ldsm_x4(af[mt][0], af[mt][1], af[mt][2], af[mt][3], addr);
                }
                uint32_t bf[4][2];
                #pragma unroll
                for (int jg = 0; jg < 2; ++jg) {
                    uint32_t addr = bbase + (uint32_t)(brow0 + jg * 16) * 128
                                  + ((bcol + 32 * ks) ^ axor);
                    ldsm_x4(bf[2 * jg][0], bf[2 * jg][1], bf[2 * jg + 1][0], bf[2 * jg + 1][1], addr);
                }
                #pragma unroll
                for (int mt = 0; mt < 4; ++mt)
                    #pragma unroll
                    for (int nt = 0; nt < 4; ++nt)
                        mma16816(acc[mt][nt], af[mt], bf[nt]);
            }

            slot = (slot + 1 == STG) ? 0 : slot + 1;
            pslot = (pslot + 1 == STG) ? 0 : pslot + 1;
        }

        // epilogue: add bias, write fp32 out
        #pragma unroll
        for (int mt = 0; mt < 4; ++mt) {
            const int r0 = m0 + wm + mt * 16 + (lane >> 2);
            #pragma unroll
            for (int nt = 0; nt < 4; ++nt) {
                const int c0 = n0 + wn + nt * 8 + 2 * (lane & 3);
                const float bv0 = g_bias[c0];
                const float bv1 = g_bias[c0 + 1];
                float2 v0 = make_float2(acc[mt][nt][0] + bv0, acc[mt][nt][1] + bv1);
                float2 v1 = make_float2(acc[mt][nt][2] + bv0, acc[mt][nt][3] + bv1);
                *reinterpret_cast<float2*>(C + (size_t)r0 * JDIM + c0) = v0;
                *reinterpret_cast<float2*>(C + (size_t)(r0 + 8) * JDIM + c0) = v1;
            }
        }
    }
}

// ---------------------------------------------------------------------------
extern "C" void kernel_launch(void* const* d_in, const int* in_sizes, int n_in,
                              void* d_out, int out_size) {
    const float* x      = (const float*)d_in[0];
    const float* coeffs = (const float*)d_in[1];
    const float* scale  = (const float*)d_in[2];
    const float* shift  = (const float*)d_in[3];
    float* out = (float*)d_out;

    pack_kernel<<<(IDIM * JDIM + 255) / 256, 256>>>(coeffs, scale);
    bias_kernel<<<IDIM / 32, 256>>>(shift);
    basis_kernel<<<(BATCH * IDIM / 8 + 255) / 256, 256>>>(x);

    cudaFuncSetAttribute(gemm_kernel, cudaFuncAttributeMaxDynamicSharedMemorySize, SMEM_DYN);
    gemm_kernel<<<GRID_CTAS, 256, SMEM_DYN>>>(out);
}

// round 15
// speedup vs baseline: 2.9608x; 1.0150x over previous
#include <cuda_runtime.h>
#include <cuda_fp16.h>
#include <cstdint>

// ---------------------------------------------------------------- constants
#define BATCH   8192
#define IDIM    768
#define JDIM    768
#define GRID_G  5
#define KDIM    (IDIM * GRID_G)      // 3840

#define BM 128                        // CTA tile M
#define BN 128                        // CTA tile N
#define BKH 64                        // fp16 K elems per chunk (128B rows)
#define NITER (KDIM / BKH)            // 60
#define MTILES (BATCH / BM)           // 64
#define NTILES_N (JDIM / BN)          // 6
#define NTILES (MTILES * NTILES_N)    // 384

#define A_TB (BM * 128)               // 16KB
#define B_TB (BN * 128)               // 16KB
#define STG 3
#define STAGE_B (A_TB + B_TB)         // 32KB
#define SMEM_DYN (STG * STAGE_B + 1024)
#define GRID_CTAS 296                 // 2 per SM x 148

// fp16 scratch (device globals -- no allocation allowed)
__device__ __half g_basis[(size_t)BATCH * KDIM];   // 63 MB   A[b][k], k = i*5+g
__device__ __half g_wt[(size_t)JDIM * KDIM];       // 5.9 MB  W^T[j][k]
__device__ float  g_bias[JDIM];
__device__ unsigned int g_ticket;

// ---------------------------------------------------------------- helpers
__device__ __forceinline__ uint32_t smem_u32(const void* p) {
    uint32_t a;
    asm("{ .reg .u64 t; cvta.to.shared.u64 t, %1; cvt.u32.u64 %0, t; }" : "=r"(a) : "l"(p));
    return a;
}
__device__ __forceinline__ void cp16(uint32_t dst, const void* src) {
    asm volatile("cp.async.cg.shared.global [%0], [%1], 16;\n" :: "r"(dst), "l"(src));
}
__device__ __forceinline__ void cp_commit() {
    asm volatile("cp.async.commit_group;\n" ::: "memory");
}
template <int N>
__device__ __forceinline__ void cp_wait() {
    asm volatile("cp.async.wait_group %0;\n" :: "n"(N) : "memory");
}
__device__ __forceinline__ void ldsm_x4(uint32_t& r0, uint32_t& r1, uint32_t& r2, uint32_t& r3,
                                        uint32_t addr) {
    asm volatile("ldmatrix.sync.aligned.m8n8.x4.shared.b16 {%0,%1,%2,%3}, [%4];"
                 : "=r"(r0), "=r"(r1), "=r"(r2), "=r"(r3) : "r"(addr));
}
__device__ __forceinline__ void mma16816(float c[4], const uint32_t a[4], const uint32_t b[2]) {
    asm volatile(
        "mma.sync.aligned.m16n8k16.row.col.f32.f16.f16.f32 "
        "{%0,%1,%2,%3}, {%4,%5,%6,%7}, {%8,%9}, {%0,%1,%2,%3};\n"
        : "+f"(c[0]), "+f"(c[1]), "+f"(c[2]), "+f"(c[3])
        : "r"(a[0]), "r"(a[1]), "r"(a[2]), "r"(a[3]), "r"(b[0]), "r"(b[1]));
}

// ---------------------------------------------------------------------------
// Kernel 1: pack W^T  g_wt[j][i*5+g] = fp16(coeffs[i,j,g] * scale[i,j])
// 32i x 32j smem-transpose tiles: coalesced reads AND coalesced writes.
// Also zeroes g_bias / ticket (runs first in stream order each replay).
// ---------------------------------------------------------------------------
#define PTI 32
#define PTJ 32
__global__ __launch_bounds__(256)
void pack_kernel(const float* __restrict__ coeffs,
                 const float* __restrict__ scale) {
    __shared__ float sc[PTI][PTJ * GRID_G];   // 20KB
    __shared__ float ss[PTI][PTJ];            // 4KB

    const int tid = threadIdx.x;
    {
        int gi = blockIdx.x * 256 + tid;
        if (gi < JDIM) g_bias[gi] = 0.f;
        if (gi == 0) g_ticket = 0u;
    }
    const int jb = JDIM / PTJ;                 // 24
    const int i0 = (blockIdx.x / jb) * PTI;
    const int j0 = (blockIdx.x % jb) * PTJ;

    // load coeffs tile: per i-row, PTJ*5 = 160 contiguous floats
    #pragma unroll
    for (int r = 0; r < (PTI * PTJ * GRID_G) / 256; ++r) {   // 20 iters
        int idx = r * 256 + tid;
        int li = idx / (PTJ * GRID_G);
        int lc = idx - li * (PTJ * GRID_G);
        sc[li][lc] = __ldg(coeffs + ((size_t)(i0 + li) * JDIM + j0) * GRID_G + lc);
    }
    // load scale tile: per i-row, 32 contiguous floats
    #pragma unroll
    for (int r = 0; r < (PTI * PTJ) / 256; ++r) {            // 4 iters
        int idx = r * 256 + tid;
        int li = idx / PTJ;
        int lj = idx - li * PTJ;
        ss[li][lj] = __ldg(scale + (size_t)(i0 + li) * JDIM + j0 + lj);
    }
    __syncthreads();

    // write: per j, PTI*5 = 160 halfs = 320B contiguous (20 x 16B)
    #pragma unroll
    for (int r = 0; r < (PTJ * 20) / 256; ++r) {             // 2.5 -> use bound
        ;
    }
    for (int idx = tid; idx < PTJ * 20; idx += 256) {        // 640 segs
        int lj  = idx / 20;
        int seg = idx - lj * 20;
        union { __half h[8]; uint4 v; } o;
        #pragma unroll
        for (int e = 0; e < 8; ++e) {
            int el = seg * 8 + e;          // 0..159
            int li = el / GRID_G;
            int g  = el - li * GRID_G;
            o.h[e] = __float2half_rn(sc[li][lj * GRID_G + g] * ss[li][lj]);
        }
        *reinterpret_cast<uint4*>(g_wt + (size_t)(j0 + lj) * KDIM + i0 * GRID_G + seg * 8) = o.v;
    }
}

// ---------------------------------------------------------------------------
// Kernel 2: bias[j] += sum over this block's 32-row i-chunk of shift[i,j]
// ---------------------------------------------------------------------------
__global__ void bias_kernel(const float* __restrict__ shift) {
    const int i0 = blockIdx.x * 32;
    #pragma unroll
    for (int jj = 0; jj < 3; ++jj) {
        const int j = jj * 256 + threadIdx.x;
        float s = 0.f;
        #pragma unroll 8
        for (int ii = 0; ii < 32; ++ii)
            s += shift[(size_t)(i0 + ii) * JDIM + j];
        atomicAdd(&g_bias[j], s);
    }
}

// ---------------------------------------------------------------------------
// Kernel 3: basis (fp16), 8 i-values per thread, 5 x 16B vector stores.
//   t=tanh(x); p=e^{-5t^2}; u=e^{5t}; v=1/u
//   exp(-5(t - grid_g)^2) = p * c_g * u^{2*grid_g};  grid = {-1,-.5,0,.5,1}
// ---------------------------------------------------------------------------
__global__ void basis_kernel(const float* __restrict__ x) {
    int idx = blockIdx.x * blockDim.x + threadIdx.x;   // over BATCH*IDIM/8
    if (idx >= BATCH * IDIM / 8) return;
    const float4 x0 = *reinterpret_cast<const float4*>(x + (size_t)idx * 8);
    const float4 x1 = *reinterpret_cast<const float4*>(x + (size_t)idx * 8 + 4);
    float xs[8] = {x0.x, x0.y, x0.z, x0.w, x1.x, x1.y, x1.z, x1.w};

    union { __half h[40]; uint4 v[5]; } out;
    const float L5 = 7.21347520444482f;                 // 5*log2(e)
    const float c1 = 0.2865047968601901f;               // e^-1.25
    const float c2 = 0.006737946999085467f;             // e^-5
    #pragma unroll
    for (int e = 0; e < 8; ++e) {
        float t, u, p, v;
        asm("tanh.approx.f32 %0, %1;" : "=f"(t) : "f"(xs[e]));
        float a = L5 * t;
        asm("ex2.approx.ftz.f32 %0, %1;" : "=f"(u) : "f"(a));
        float na = -a * t;                               // -5*log2(e)*t^2
        asm("ex2.approx.ftz.f32 %0, %1;" : "=f"(p) : "f"(na));
        asm("rcp.approx.ftz.f32 %0, %1;" : "=f"(v) : "f"(u));
        out.h[e * 5 + 0] = __float2half_rn(p * c2 * v * v);
        out.h[e * 5 + 1] = __float2half_rn(p * c1 * v);
        out.h[e * 5 + 2] = __float2half_rn(p);
        out.h[e * 5 + 3] = __float2half_rn(p * c1 * u);
        out.h[e * 5 + 4] = __float2half_rn(p * c2 * u * u);
    }
    uint4* dst = reinterpret_cast<uint4*>(g_basis + (size_t)idx * 40);
    #pragma unroll
    for (int q = 0; q < 5; ++q) dst[q] = out.v[q];
}

// ---------------------------------------------------------------------------
// Kernel 4: GEMM  C[b,j] = sum_k A[b,k] W^T[j,k] + bias[j]
// 128x128 CTA tiles, 4 warps at 64x64 each (2x2), atomic-ticket scheduler,
// 3-stage cp.async, 1 sync per K chunk. Halves LDSM fragment traffic.
// ---------------------------------------------------------------------------
__global__ __launch_bounds__(128, 2)
void gemm_kernel(float* __restrict__ C) {
    extern __shared__ char dsmem[];
    __shared__ unsigned s_tile;
    const uint32_t sbase = (smem_u32(dsmem) + 1023u) & ~1023u;

    const int tid  = threadIdx.x;
    const int lane = tid & 31;
    const int wid  = tid >> 5;            // 0..3
    const int wm   = (wid & 1) * 64;      // 2x2 warps of 64x64
    const int wn   = (wid >> 1) * 64;

    // staging indices (per stage: A 128 rows + B 128 rows, 128B each)
    const int srow = tid >> 3;                       // 0..15
    const int sseg = (tid & 7) * 16;                 // byte col 0..112
    const uint32_t swcol = (uint32_t)(sseg ^ ((srow & 7) << 4));
    const int scol_h = sseg >> 1;                    // half offset within row

    // ldmatrix lane addressing (verified maps)
    const int arow0 = wm + (lane & 7) + 8 * ((lane >> 3) & 1);    // + mt*16
    const uint32_t axor = (uint32_t)((lane & 7) << 4);
    const uint32_t acol = (uint32_t)(16 * (lane >> 4));           // + 32*ks
    const int brow0 = wn + (lane & 7) + 8 * (lane >> 4);          // + jg*16
    const uint32_t bcol = (uint32_t)(16 * ((lane >> 3) & 1));     // + 32*ks

    for (;;) {
        if (tid == 0) s_tile = atomicAdd(&g_ticket, 1u);
        __syncthreads();                 // also guards smem reuse across tiles
        const unsigned t = s_tile;
        if (t >= NTILES) break;
        const int m0 = (int)(t / NTILES_N) * BM;
        const int n0 = (int)(t % NTILES_N) * BN;

        const __half* aglob = g_basis + (size_t)(m0 + srow) * KDIM + scol_h;
        const __half* bglob = g_wt   + (size_t)(n0 + srow) * KDIM + scol_h;

        float acc[4][8][4];
        #pragma unroll
        for (int mt = 0; mt < 4; ++mt)
            #pragma unroll
            for (int nt = 0; nt < 8; ++nt)
                #pragma unroll
                for (int r = 0; r < 4; ++r) acc[mt][nt][r] = 0.f;

        // prologue: chunks 0 and 1
        #pragma unroll
        for (int pc = 0; pc < 2; ++pc) {
            const uint32_t sb = sbase + pc * STAGE_B;
            #pragma unroll
            for (int q = 0; q < 8; ++q)
                cp16(sb + (srow + 16 * q) * 128 + swcol, aglob + pc * BKH + (size_t)(16 * q) * KDIM);
            #pragma unroll
            for (int q = 0; q < 8; ++q)
                cp16(sb + A_TB + (srow + 16 * q) * 128 + swcol, bglob + pc * BKH + (size_t)(16 * q) * KDIM);
            cp_commit();
        }

        int slot = 0, pslot = 2;
        for (int kt = 0; kt < NITER; ++kt) {
            cp_wait<1>();
            __syncthreads();

            // prefetch chunk kt+2 into pslot
            if (kt + 2 < NITER) {
                const int kh = (kt + 2) * BKH;
                const uint32_t sb = sbase + pslot * STAGE_B;
                #pragma unroll
                for (int q = 0; q < 8; ++q)
                    cp16(sb + (srow + 16 * q) * 128 + swcol, aglob + kh + (size_t)(16 * q) * KDIM);
                #pragma unroll
                for (int q = 0; q < 8; ++q)
                    cp16(sb + A_TB + (srow + 16 * q) * 128 + swcol, bglob + kh + (size_t)(16 * q) * KDIM);
            }
            cp_commit();   // always: keeps exactly 2 groups pending

            const uint32_t abase = sbase + slot * STAGE_B;
            const uint32_t bbase = abase + A_TB;

            #pragma unroll
            for (int ks = 0; ks < 4; ++ks) {
                uint32_t af[4][4];
                #pragma unroll
                for (int mt = 0; mt < 4; ++mt) {
                    uint32_t addr = abase + (uint32_t)(arow0 + mt * 16) * 128
                                  + ((acol + 32 * ks) ^ axor);
                    ldsm_x4(af[mt][0], af[mt][1], af[mt][2], af[mt][3], addr);
                }
                uint32_t bf[8][2];
                #pragma unroll
                for (int jg = 0; jg < 4; ++jg) {
                    uint32_t addr = bbase + (uint32_t)(brow0 + jg * 16) * 128
                                  + ((bcol + 32 * ks) ^ axor);
                    ldsm_x4(bf[2 * jg][0], bf[2 * jg][1], bf[2 * jg + 1][0], bf[2 * jg + 1][1], addr);
                }
                #pragma unroll
                for (int mt = 0; mt < 4; ++mt)
                    #pragma unroll
                    for (int nt = 0; nt < 8; ++nt)
                        mma16816(acc[mt][nt], af[mt], bf[nt]);
            }

            slot = (slot + 1 == STG) ? 0 : slot + 1;
            pslot = (pslot + 1 == STG) ? 0 : pslot + 1;
        }

        // epilogue: add bias, write fp32 out
        #pragma unroll
        for (int mt = 0; mt < 4; ++mt) {
            const int r0 = m0 + wm + mt * 16 + (lane >> 2);
            #pragma unroll
            for (int nt = 0; nt < 8; ++nt) {
                const int c0 = n0 + wn + nt * 8 + 2 * (lane & 3);
                const float bv0 = g_bias[c0];
                const float bv1 = g_bias[c0 + 1];
                float2 v0 = make_float2(acc[mt][nt][0] + bv0, acc[mt][nt][1] + bv1);
                float2 v1 = make_float2(acc[mt][nt][2] + bv0, acc[mt][nt][3] + bv1);
                *reinterpret_cast<float2*>(C + (size_t)r0 * JDIM + c0) = v0;
                *reinterpret_cast<float2*>(C + (size_t)(r0 + 8) * JDIM + c0) = v1;
            }
        }
    }
}

// ---------------------------------------------------------------------------
extern "C" void kernel_launch(void* const* d_in, const int* in_sizes, int n_in,
                              void* d_out, int out_size) {
    const float* x      = (const float*)d_in[0];
    const float* coeffs = (const float*)d_in[1];
    const float* scale  = (const float*)d_in[2];
    const float* shift  = (const float*)d_in[3];
    float* out = (float*)d_out;

    pack_kernel<<<(IDIM / PTI) * (JDIM / PTJ), 256>>>(coeffs, scale);
    bias_kernel<<<IDIM / 32, 256>>>(shift);
    basis_kernel<<<(BATCH * IDIM / 8 + 255) / 256, 256>>>(x);

    cudaFuncSetAttribute(gemm_kernel, cudaFuncAttributeMaxDynamicSharedMemorySize, SMEM_DYN);
    gemm_kernel<<<GRID_CTAS, 128, SMEM_DYN>>>(out);
}